// round 1
// baseline (speedup 1.0000x reference)
#include <cuda_runtime.h>
#include <cstdint>

typedef unsigned long long ull;

#define NH 4
#define HD 32
#define PX 68    // Xst / Ot pitch (floats)
#define PW 132   // staged weight pitch
#define PQ 132   // Q/K/V/Y pitch
#define SC_Q 0.17677669529663687f  // 32^-0.5

// packed fp32x2 FMA (sm_10x): doubles fp32 throughput vs FFMA
__device__ __forceinline__ void fma2(ull &d, ull a, ull b) {
    asm volatile("fma.rn.f32x2 %0, %1, %2, %0;" : "+l"(d) : "l"(a), "l"(b));
}
__device__ __forceinline__ ull pack2(float x) {
    ull d; unsigned u = __float_as_uint(x);
    asm volatile("mov.b64 %0, {%1, %1};" : "=l"(d) : "r"(u));
    return d;
}
__device__ __forceinline__ float2 unpack2(ull d) {
    float2 r;
    asm volatile("mov.b64 {%0, %1}, %2;" : "=f"(r.x), "=f"(r.y) : "l"(d));
    return r;
}

// smem layout (floats): Xst[128*PX] | Ws[128*PW] | Qs[64*PQ] | Ks | Vs | Bt[900]
#define SMEM_FLOATS (128*PX + 128*PW + 3*64*PQ + 900)

__global__ void __launch_bounds__(256, 1)
wattn_kernel(const float* __restrict__ x, const float* __restrict__ qkv_w,
             const float* __restrict__ qkv_b, const float* __restrict__ proj_w,
             const float* __restrict__ proj_b, const float* __restrict__ rpb,
             float* __restrict__ out)
{
    extern __shared__ float sm[];
    float* Xst = sm;                 // [128][PX]  input (k-major), later attn output (k-major)
    float* Ws  = Xst + 128*PX;       // [128][PW]  staged weights, Ws[k][j]
    float* Qs  = Ws  + 128*PW;       // [64][PQ]   Q (prescaled), later final Y
    float* Ks  = Qs  + 64*PQ;
    float* Vs  = Ks  + 64*PQ;
    float* Bt  = Vs  + 64*PQ;        // rpb table [225*4]

    const int tid = threadIdx.x;
    int wid = blockIdx.x;
    const int wn = wid & 7;  wid >>= 3;
    const int hn = wid & 7;  wid >>= 3;
    const int v  = wid % 5;  wid /= 5;
    const int u  = wid % 5;
    const int b  = wid / 5;

    // base for (b, c=0, u, v): layout (B,C,U,V,H,W), C-stride = 25*4096 = 102400
    const int base = (((b << 7) * 5 + u) * 5 + v) * 4096;
    const float* xb = x + base;

    // ---- Phase 1: roll + window gather into Xst[c][s] ----
    #pragma unroll
    for (int i = tid; i < 8192; i += 256) {
        int c = i >> 6, s = i & 63;
        int sh = ((hn << 3) + (s >> 3) - 4) & 63;
        int sw = ((wn << 3) + (s & 7) - 4) & 63;
        Xst[c * PX + s] = __ldg(xb + c * 102400 + sh * 64 + sw);
    }
    for (int i = tid; i < 900; i += 256) Bt[i] = rpb[i];
    __syncthreads();

    // weight stager: Ws[k][j] = gw[j*128 + k]   (all 256 threads)
    auto stageW = [&](const float* gw) {
        int j  = tid >> 1;
        int k0 = (tid & 1) << 6;
        const float4* src = reinterpret_cast<const float4*>(gw + j * 128 + k0);
        #pragma unroll
        for (int i = 0; i < 16; i++) {
            float4 w4 = src[i];
            int k = k0 + (i << 2);
            Ws[(k + 0) * PW + j] = w4.x;
            Ws[(k + 1) * PW + j] = w4.y;
            Ws[(k + 2) * PW + j] = w4.z;
            Ws[(k + 3) * PW + j] = w4.w;
        }
    };

    // GEMM core: 128 threads, 8 rows x 8 cols per thread (cols split ct*4 and 64+ct*4
    // for conflict-free LDS.128). Result: acc[8][4] of f32x2 pairs.
    const int rt = tid >> 4;   // 0..7 (valid when tid < 128)
    const int ct = tid & 15;   // 0..15

    auto gemm_core = [&](const float* A, int pa, ull acc[8][4]) {
        #pragma unroll
        for (int r = 0; r < 8; r++)
            #pragma unroll
            for (int p = 0; p < 4; p++) acc[r][p] = 0ULL;
        #pragma unroll 4
        for (int k = 0; k < 128; k++) {
            const float* Ar = A + k * pa + rt * 8;
            float4 a0 = *(const float4*)(Ar);
            float4 a1 = *(const float4*)(Ar + 4);
            const ulonglong2* Br = (const ulonglong2*)(Ws + k * PW);
            ulonglong2 bA = Br[ct];        // cols ct*4 .. ct*4+3
            ulonglong2 bB = Br[16 + ct];   // cols 64+ct*4 ..
            float ar[8] = {a0.x, a0.y, a0.z, a0.w, a1.x, a1.y, a1.z, a1.w};
            #pragma unroll
            for (int r = 0; r < 8; r++) {
                ull ap = pack2(ar[r]);
                fma2(acc[r][0], ap, bA.x);
                fma2(acc[r][1], ap, bA.y);
                fma2(acc[r][2], ap, bB.x);
                fma2(acc[r][3], ap, bB.y);
            }
        }
    };

    // ---- Phase 2: QKV = Xw @ qkv_w^T + b, interleaved-head layout ----
    // global channel j in [0,384): h=j/96, r=j%96, seg=r/32 (0=q,1=k,2=v), col=h*32+(r%32)
    #pragma unroll 1
    for (int p = 0; p < 3; p++) {
        stageW(qkv_w + p * 16384);
        __syncthreads();
        if (tid < 128) {
            ull acc[8][4];
            gemm_core(Xst, PX, acc);
            #pragma unroll
            for (int g = 0; g < 2; g++) {
                int j   = p * 128 + g * 64 + ct * 4;
                int hh  = j / 96;
                int r   = j - hh * 96;
                int seg = r >> 5;
                int col = hh * 32 + (r & 31);
                float* dst = (seg == 0) ? Qs : (seg == 1) ? Ks : Vs;
                float sc   = (seg == 0) ? SC_Q : 1.0f;
                float4 b4  = *(const float4*)(qkv_b + j);
                #pragma unroll
                for (int r8 = 0; r8 < 8; r8++) {
                    int s = rt * 8 + r8;
                    float2 p0 = unpack2(acc[r8][g * 2 + 0]);
                    float2 p1 = unpack2(acc[r8][g * 2 + 1]);
                    float4 o;
                    o.x = (p0.x + b4.x) * sc;
                    o.y = (p0.y + b4.y) * sc;
                    o.z = (p1.x + b4.z) * sc;
                    o.w = (p1.y + b4.w) * sc;
                    *(float4*)(dst + s * PQ + col) = o;
                }
            }
        }
        __syncthreads();
    }

    // stage proj weights now (Ws free; overlaps ahead of attention)
    stageW(proj_w);

    // ---- Phase 3: attention. thread = (head h, query q). exact softmax. ----
    {
        const int h = tid >> 6;
        const int q = tid & 63;
        ull qp[16];
        const ull* qrow = (const ull*)(Qs + q * PQ + h * HD);
        #pragma unroll
        for (int d = 0; d < 16; d++) qp[d] = qrow[d];

        float lg[64];
        const int qi = q >> 3, qj = q & 7;
        #pragma unroll
        for (int t = 0; t < 64; t++) {
            const ull* kr = (const ull*)(Ks + t * PQ + h * HD);
            ull a = 0ULL;
            #pragma unroll
            for (int d = 0; d < 16; d++) fma2(a, qp[d], kr[d]);
            float2 s2 = unpack2(a);
            int ridx = (qi - (t >> 3) + 7) * 15 + (qj - (t & 7) + 7);
            lg[t] = s2.x + s2.y + Bt[ridx * 4 + h];
        }
        float m = lg[0];
        #pragma unroll
        for (int t = 1; t < 64; t++) m = fmaxf(m, lg[t]);
        float l = 0.f;
        #pragma unroll
        for (int t = 0; t < 64; t++) { float e = __expf(lg[t] - m); lg[t] = e; l += e; }
        float inv = __fdividef(1.0f, l);

        ull op[16];
        #pragma unroll
        for (int d = 0; d < 16; d++) op[d] = 0ULL;
        #pragma unroll
        for (int t = 0; t < 64; t++) {
            ull pp = pack2(lg[t]);
            const ull* vr = (const ull*)(Vs + t * PQ + h * HD);
            #pragma unroll
            for (int d = 0; d < 16; d++) fma2(op[d], pp, vr[d]);
        }
        // write attention output transposed (k-major) into Xst for proj GEMM
        #pragma unroll
        for (int d = 0; d < 16; d++) {
            float2 o2 = unpack2(op[d]);
            int c = h * HD + 2 * d;
            Xst[c * PX + q]       = o2.x * inv;
            Xst[(c + 1) * PX + q] = o2.y * inv;
        }
    }
    __syncthreads();

    // ---- Phase 4: proj GEMM -> Y into Qs buffer ----
    if (tid < 128) {
        ull acc[8][4];
        gemm_core(Xst, PX, acc);
        #pragma unroll
        for (int g = 0; g < 2; g++) {
            int j = g * 64 + ct * 4;
            float4 b4 = *(const float4*)(proj_b + j);
            #pragma unroll
            for (int r8 = 0; r8 < 8; r8++) {
                int s = rt * 8 + r8;
                float2 p0 = unpack2(acc[r8][g * 2 + 0]);
                float2 p1 = unpack2(acc[r8][g * 2 + 1]);
                float4 o;
                o.x = p0.x + b4.x;
                o.y = p0.y + b4.y;
                o.z = p1.x + b4.z;
                o.w = p1.y + b4.w;
                *(float4*)(Qs + s * PQ + j) = o;
            }
        }
    }
    __syncthreads();

    // ---- Phase 5: coalesced reverse-roll scatter ----
    float* ob = out + base;
    #pragma unroll
    for (int i = tid; i < 8192; i += 256) {
        int c = i >> 6, s = i & 63;
        int sh = ((hn << 3) + (s >> 3) - 4) & 63;
        int sw = ((wn << 3) + (s & 7) - 4) & 63;
        ob[c * 102400 + sh * 64 + sw] = Qs[s * PQ + c];
    }
}

extern "C" void kernel_launch(void* const* d_in, const int* in_sizes, int n_in,
                              void* d_out, int out_size) {
    (void)in_sizes; (void)n_in; (void)out_size;
    size_t smem = SMEM_FLOATS * sizeof(float);
    cudaFuncSetAttribute(wattn_kernel, cudaFuncAttributeMaxDynamicSharedMemorySize, (int)smem);
    wattn_kernel<<<3200, 256, smem>>>(
        (const float*)d_in[0], (const float*)d_in[1], (const float*)d_in[2],
        (const float*)d_in[3], (const float*)d_in[4], (const float*)d_in[5],
        (float*)d_out);
}

// round 2
// speedup vs baseline: 1.0020x; 1.0020x over previous
#include <cuda_runtime.h>
#include <cstdint>

typedef unsigned long long ull;

#define NH 4
#define HD 32
#define PX 68    // Xst / Ot pitch (floats)
#define PW 132   // staged weight pitch
#define PQ 132   // Q/K/V/Y pitch
#define SC_Q 0.17677669529663687f  // 32^-0.5

// packed fp32x2 FMA (sm_10x): doubles fp32 throughput vs FFMA
__device__ __forceinline__ void fma2(ull &d, ull a, ull b) {
    asm volatile("fma.rn.f32x2 %0, %1, %2, %0;" : "+l"(d) : "l"(a), "l"(b));
}
__device__ __forceinline__ ull pack2(float x) {
    ull d; unsigned u = __float_as_uint(x);
    asm volatile("mov.b64 %0, {%1, %1};" : "=l"(d) : "r"(u));
    return d;
}
__device__ __forceinline__ float2 unpack2(ull d) {
    float2 r;
    asm volatile("mov.b64 {%0, %1}, %2;" : "=f"(r.x), "=f"(r.y) : "l"(d));
    return r;
}

// smem layout (floats): Xst[128*PX] | Ws[128*PW] | Qs[64*PQ] | Ks | Vs | Bt[900]
#define SMEM_FLOATS (128*PX + 128*PW + 3*64*PQ + 900)

__global__ void __launch_bounds__(256, 1)
wattn_kernel(const float* __restrict__ x, const float* __restrict__ qkv_w,
             const float* __restrict__ qkv_b, const float* __restrict__ proj_w,
             const float* __restrict__ proj_b, const float* __restrict__ rpb,
             float* __restrict__ out)
{
    extern __shared__ float sm[];
    float* Xst = sm;                 // [128][PX]  input (k-major), later attn output (k-major)
    float* Ws  = Xst + 128*PX;       // [128][PW]  staged weights, Ws[k][j]
    float* Qs  = Ws  + 128*PW;       // [64][PQ]   Q (prescaled), later final Y
    float* Ks  = Qs  + 64*PQ;
    float* Vs  = Ks  + 64*PQ;
    float* Bt  = Vs  + 64*PQ;        // rpb table [225*4]

    const int tid = threadIdx.x;
    int wid = blockIdx.x;
    const int wn = wid & 7;  wid >>= 3;
    const int hn = wid & 7;  wid >>= 3;
    const int v  = wid % 5;  wid /= 5;
    const int u  = wid % 5;
    const int b  = wid / 5;

    // base for (b, c=0, u, v): layout (B,C,U,V,H,W), C-stride = 25*4096 = 102400
    const int base = (((b << 7) * 5 + u) * 5 + v) * 4096;
    const float* xb = x + base;

    // ---- Phase 1: roll + window gather into Xst[c][s] ----
    #pragma unroll
    for (int i = tid; i < 8192; i += 256) {
        int c = i >> 6, s = i & 63;
        int sh = ((hn << 3) + (s >> 3) - 4) & 63;
        int sw = ((wn << 3) + (s & 7) - 4) & 63;
        Xst[c * PX + s] = __ldg(xb + c * 102400 + sh * 64 + sw);
    }
    for (int i = tid; i < 900; i += 256) Bt[i] = rpb[i];
    __syncthreads();

    // weight stager: Ws[k][j] = gw[j*128 + k]   (all 256 threads)
    auto stageW = [&](const float* gw) {
        int j  = tid >> 1;
        int k0 = (tid & 1) << 6;
        const float4* src = reinterpret_cast<const float4*>(gw + j * 128 + k0);
        #pragma unroll
        for (int i = 0; i < 16; i++) {
            float4 w4 = src[i];
            int k = k0 + (i << 2);
            Ws[(k + 0) * PW + j] = w4.x;
            Ws[(k + 1) * PW + j] = w4.y;
            Ws[(k + 2) * PW + j] = w4.z;
            Ws[(k + 3) * PW + j] = w4.w;
        }
    };

    // GEMM core: 128 threads, 8 rows x 8 cols per thread (cols split ct*4 and 64+ct*4
    // for conflict-free LDS.128). Result: acc[8][4] of f32x2 pairs.
    const int rt = tid >> 4;   // 0..7 (valid when tid < 128)
    const int ct = tid & 15;   // 0..15

    auto gemm_core = [&](const float* A, int pa, ull acc[8][4]) {
        #pragma unroll
        for (int r = 0; r < 8; r++)
            #pragma unroll
            for (int p = 0; p < 4; p++) acc[r][p] = 0ULL;
        #pragma unroll 4
        for (int k = 0; k < 128; k++) {
            const float* Ar = A + k * pa + rt * 8;
            float4 a0 = *(const float4*)(Ar);
            float4 a1 = *(const float4*)(Ar + 4);
            const ulonglong2* Br = (const ulonglong2*)(Ws + k * PW);
            ulonglong2 bA = Br[ct];        // cols ct*4 .. ct*4+3
            ulonglong2 bB = Br[16 + ct];   // cols 64+ct*4 ..
            float ar[8] = {a0.x, a0.y, a0.z, a0.w, a1.x, a1.y, a1.z, a1.w};
            #pragma unroll
            for (int r = 0; r < 8; r++) {
                ull ap = pack2(ar[r]);
                fma2(acc[r][0], ap, bA.x);
                fma2(acc[r][1], ap, bA.y);
                fma2(acc[r][2], ap, bB.x);
                fma2(acc[r][3], ap, bB.y);
            }
        }
    };

    // ---- Phase 2: QKV = Xw @ qkv_w^T + b, interleaved-head layout ----
    // global channel j in [0,384): h=j/96, r=j%96, seg=r/32 (0=q,1=k,2=v), col=h*32+(r%32)
    #pragma unroll 1
    for (int p = 0; p < 3; p++) {
        stageW(qkv_w + p * 16384);
        __syncthreads();
        if (tid < 128) {
            ull acc[8][4];
            gemm_core(Xst, PX, acc);
            #pragma unroll
            for (int g = 0; g < 2; g++) {
                int j   = p * 128 + g * 64 + ct * 4;
                int hh  = j / 96;
                int r   = j - hh * 96;
                int seg = r >> 5;
                int col = hh * 32 + (r & 31);
                float* dst = (seg == 0) ? Qs : (seg == 1) ? Ks : Vs;
                float sc   = (seg == 0) ? SC_Q : 1.0f;
                float4 b4  = *(const float4*)(qkv_b + j);
                #pragma unroll
                for (int r8 = 0; r8 < 8; r8++) {
                    int s = rt * 8 + r8;
                    float2 p0 = unpack2(acc[r8][g * 2 + 0]);
                    float2 p1 = unpack2(acc[r8][g * 2 + 1]);
                    float4 o;
                    o.x = (p0.x + b4.x) * sc;
                    o.y = (p0.y + b4.y) * sc;
                    o.z = (p1.x + b4.z) * sc;
                    o.w = (p1.y + b4.w) * sc;
                    *(float4*)(dst + s * PQ + col) = o;
                }
            }
        }
        __syncthreads();
    }

    // stage proj weights now (Ws free; overlaps ahead of attention)
    stageW(proj_w);

    // ---- Phase 3: attention. thread = (head h, query q). exact softmax. ----
    {
        const int h = tid >> 6;
        const int q = tid & 63;
        ull qp[16];
        const ull* qrow = (const ull*)(Qs + q * PQ + h * HD);
        #pragma unroll
        for (int d = 0; d < 16; d++) qp[d] = qrow[d];

        float lg[64];
        const int qi = q >> 3, qj = q & 7;
        #pragma unroll
        for (int t = 0; t < 64; t++) {
            const ull* kr = (const ull*)(Ks + t * PQ + h * HD);
            ull a = 0ULL;
            #pragma unroll
            for (int d = 0; d < 16; d++) fma2(a, qp[d], kr[d]);
            float2 s2 = unpack2(a);
            int ridx = (qi - (t >> 3) + 7) * 15 + (qj - (t & 7) + 7);
            lg[t] = s2.x + s2.y + Bt[ridx * 4 + h];
        }
        float m = lg[0];
        #pragma unroll
        for (int t = 1; t < 64; t++) m = fmaxf(m, lg[t]);
        float l = 0.f;
        #pragma unroll
        for (int t = 0; t < 64; t++) { float e = __expf(lg[t] - m); lg[t] = e; l += e; }
        float inv = __fdividef(1.0f, l);

        ull op[16];
        #pragma unroll
        for (int d = 0; d < 16; d++) op[d] = 0ULL;
        #pragma unroll
        for (int t = 0; t < 64; t++) {
            ull pp = pack2(lg[t]);
            const ull* vr = (const ull*)(Vs + t * PQ + h * HD);
            #pragma unroll
            for (int d = 0; d < 16; d++) fma2(op[d], pp, vr[d]);
        }
        // write attention output transposed (k-major) into Xst for proj GEMM
        #pragma unroll
        for (int d = 0; d < 16; d++) {
            float2 o2 = unpack2(op[d]);
            int c = h * HD + 2 * d;
            Xst[c * PX + q]       = o2.x * inv;
            Xst[(c + 1) * PX + q] = o2.y * inv;
        }
    }
    __syncthreads();

    // ---- Phase 4: proj GEMM -> Y into Qs buffer ----
    if (tid < 128) {
        ull acc[8][4];
        gemm_core(Xst, PX, acc);
        #pragma unroll
        for (int g = 0; g < 2; g++) {
            int j = g * 64 + ct * 4;
            float4 b4 = *(const float4*)(proj_b + j);
            #pragma unroll
            for (int r8 = 0; r8 < 8; r8++) {
                int s = rt * 8 + r8;
                float2 p0 = unpack2(acc[r8][g * 2 + 0]);
                float2 p1 = unpack2(acc[r8][g * 2 + 1]);
                float4 o;
                o.x = p0.x + b4.x;
                o.y = p0.y + b4.y;
                o.z = p1.x + b4.z;
                o.w = p1.y + b4.w;
                *(float4*)(Qs + s * PQ + j) = o;
            }
        }
    }
    __syncthreads();

    // ---- Phase 5: coalesced reverse-roll scatter ----
    float* ob = out + base;
    #pragma unroll
    for (int i = tid; i < 8192; i += 256) {
        int c = i >> 6, s = i & 63;
        int sh = ((hn << 3) + (s >> 3) - 4) & 63;
        int sw = ((wn << 3) + (s & 7) - 4) & 63;
        ob[c * 102400 + sh * 64 + sw] = Qs[s * PQ + c];
    }
}

extern "C" void kernel_launch(void* const* d_in, const int* in_sizes, int n_in,
                              void* d_out, int out_size) {
    (void)in_sizes; (void)n_in; (void)out_size;
    size_t smem = SMEM_FLOATS * sizeof(float);
    cudaFuncSetAttribute(wattn_kernel, cudaFuncAttributeMaxDynamicSharedMemorySize, (int)smem);
    wattn_kernel<<<3200, 256, smem>>>(
        (const float*)d_in[0], (const float*)d_in[1], (const float*)d_in[2],
        (const float*)d_in[3], (const float*)d_in[4], (const float*)d_in[5],
        (float*)d_out);
}